// round 13
// baseline (speedup 1.0000x reference)
#include <cuda_runtime.h>
#include <cstdint>

// DetectPeaksTM: per-row sliding max (K=301) NMS + top-2 (value, index).
// Persistent grid-stride kernel (444 CTAs, 512 threads, 3 CTAs/SM).
// Per row: all warps front-batch 4 LDG.128s, REDUX -> tileMax[k&1], ONE
// barrier, then warps 1..15 start row k+1's loads while warp 0 runs row k's
// candidate selection (survivor == max of its aligned 128-tile; index
// recovered lazily from the L2-hot row).

#define NT     8192
#define HALF   150
#define WIN    301
#define NROWS  6144
#define GRID   444          // 148 SMs * 3 CTAs

typedef unsigned long long u64;
typedef unsigned int u32;

__device__ __forceinline__ u32 absbits(float f) {
    return __float_as_uint(f) & 0x7fffffffu;
}
__device__ __forceinline__ u64 umax64(u64 a, u64 b) { return a > b ? a : b; }
__device__ __forceinline__ u64 shfl_xor_u64(u64 v, int d) {
    u32 lo = (u32)v, hi = (u32)(v >> 32);
    lo = __shfl_xor_sync(0xffffffffu, lo, d);
    hi = __shfl_xor_sync(0xffffffffu, hi, d);
    return ((u64)hi << 32) | lo;
}

// First index > bound inside tile whose absbits == val, or -1.
__device__ __forceinline__ int find_next(u32 em, int tile, int bound, int lane) {
    int base = tile * 128 + lane * 4;
    int rel = bound - base;                  // element j excluded iff j <= rel
    u32 emm = em;
    if (rel >= 3) emm = 0;
    else if (rel >= 0) emm &= (0xFu << (rel + 1));
    u32 bl = __ballot_sync(0xffffffffu, emm != 0);
    if (!bl) return -1;
    int lf = __ffs((int)bl) - 1;
    u32 pk = __shfl_sync(0xffffffffu, emm, lf);
    return tile * 128 + lf * 4 + (__ffs((int)pk) - 1);
}

__device__ void select_row(const float* __restrict__ xr,
                           const u32* __restrict__ tmx,
                           float* __restrict__ out, int row, int lane) {
    const u32 FULL = 0xffffffffu;
    u64 keys[2];
#pragma unroll
    for (int q = 0; q < 2; q++) {
        int t = lane + 32 * q;
        keys[q] = ((u64)tmx[t] << 32) | (u32)(~(u32)(t * 128));
    }
    u64 pend = 0;
    int pendIdx = -1;

    float rv0 = 0.0f, rv1 = 0.0f;
    int   ri0 = 0,    ri1 = 0;
    int found = 0;

    for (int it = 0; it < 192 && found < 2; it++) {
        u64 best = umax64(umax64(keys[0], keys[1]), pend);
#pragma unroll
        for (int s = 16; s > 0; s >>= 1) best = umax64(best, shfl_xor_u64(best, s));
        if (best == 0ull) break;

        bool wasPend = (best == pend && pend != 0ull);
        if (wasPend) pend = 0;
        if (keys[0] == best) keys[0] = 0;
        if (keys[1] == best) keys[1] = 0;

        u32 val = (u32)(best >> 32);
        int tile, idxV;
        if (wasPend) { idxV = pendIdx; tile = idxV >> 7; }
        else         { tile = (int)((~(u32)(best & 0xffffffffull)) >> 7); idxV = -1; }

        // rescan tile for occurrence chain (L2-hot)
        float4 tv = ((const float4*)(xr + tile * 128))[lane];
        u32 em = (u32)(absbits(tv.x) == val)        |
                 ((u32)(absbits(tv.y) == val) << 1) |
                 ((u32)(absbits(tv.z) == val) << 2) |
                 ((u32)(absbits(tv.w) == val) << 3);
        if (!wasPend) idxV = find_next(em, tile, tile * 128 - 1, lane);
        int nxt = find_next(em, tile, idxV, lane);
        if (nxt >= 0) { pend = ((u64)val << 32) | (u32)(~(u32)nxt); pendIdx = nxt; }

        // verify idxV against window max using tile bounds (smem)
        int lo = max(idxV - HALF, 0);
        int hi = min(idxV + HALF, NT - 1);
        int ta = lo >> 7, tb = hi >> 7;
        int t = ta + lane;
        u32 tm = (t <= tb) ? tmx[t] : 0u;
        u32 bound = __reduce_max_sync(FULL, tm);

        bool accept = (bound <= val);
        if (!accept) {
            bool fullt = (t <= tb) && (t * 128 >= lo) && (t * 128 + 127 <= hi);
            if (__reduce_max_sync(FULL, fullt ? tm : 0u) > val) continue;
            // ambiguous edge tiles: exact window max from gmem (rare)
            u32 mbx = 0;
            int base = idxV - HALF;
#pragma unroll
            for (int rr = 0; rr < 10; rr++) {
                int off = lane + 32 * rr;
                int p = min(max(base + off, 0), NT - 1);
                u32 xb = absbits(__ldg(xr + p));
                if (off < WIN) mbx = max(mbx, xb);
            }
            if (__reduce_max_sync(FULL, mbx) > val) continue;
            accept = true;
        }

        if (found == 0) { rv0 = __uint_as_float(val); ri0 = idxV; }
        else            { rv1 = __uint_as_float(val); ri1 = idxV; }
        found++;
    }

    if (lane == 0) {
        if (found < 2) {
            rv1 = 0.0f;
            ri1 = (found >= 1 && ri0 == 0) ? 1 : 0;
        }
        out[row * 2 + 0] = rv0;
        out[row * 2 + 1] = rv1;
        out[(size_t)NROWS * 2 + row * 2 + 0] = (float)ri0;
        out[(size_t)NROWS * 2 + row * 2 + 1] = (float)ri1;
    }
}

__global__ void __launch_bounds__(512, 3)
detect_peaks_kernel(const float* __restrict__ x, float* __restrict__ out) {
    __shared__ u32 tileMax[2][64];

    const int tid  = threadIdx.x;
    const int lane = tid & 31;
    const int warp = tid >> 5;               // 0..15
    const u32 FULL = 0xffffffffu;

    int buf = 0;
    for (int row = blockIdx.x; row < NROWS; row += GRID, buf ^= 1) {
        const float* xr = x + (size_t)row * NT;
        const float4* src = (const float4*)xr;

        float4 v[4];
#pragma unroll
        for (int k = 0; k < 4; k++) v[k] = src[tid + 512 * k];

#pragma unroll
        for (int k = 0; k < 4; k++) {
            float m01 = fmaxf(fabsf(v[k].x), fabsf(v[k].y));
            float m23 = fmaxf(fabsf(v[k].z), fabsf(v[k].w));
            float m   = fmaxf(m01, m23);
            u32 m1 = __reduce_max_sync(FULL, __float_as_uint(m));
            if (lane == 0) tileMax[buf][warp + 16 * k] = m1;
        }
        __syncthreads();
        // warps 1..15 proceed to row+GRID loads while warp 0 selects.
        // tileMax double-buffering makes the WAR safe: buffer `buf` is next
        // written at iter+2, whose writers passed iter+1's barrier, which
        // warp 0 only reaches after finishing these reads.
        if (warp == 0)
            select_row(xr, tileMax[buf], out, row, lane);
    }
}

extern "C" void kernel_launch(void* const* d_in, const int* in_sizes, int n_in,
                              void* d_out, int out_size) {
    const float* x = (const float*)d_in[0];
    float* out = (float*)d_out;
    detect_peaks_kernel<<<GRID, 512>>>(x, out);
}

// round 14
// speedup vs baseline: 1.1913x; 1.1913x over previous
#include <cuda_runtime.h>
#include <cstdint>

// DetectPeaksTM: per-row sliding max (K=301) NMS + top-2 (value, index).
// Candidate-based (survivor == max of its aligned 128-tile). One row per
// 256-thread CTA, dual-path streaming: first half-row (16KB) via TMA into
// smem, second half via front-batched LDG.128s (reduced before the mbarrier
// wait, overlapping TMA arrival). Small smem (~16.6KB) + launch_bounds(256,8)
// maximizes per-SM outstanding transfers.

#define NT    8192
#define HALFN 4096
#define HALF  150
#define WIN   301

typedef unsigned long long u64;
typedef unsigned int u32;

__device__ __forceinline__ u32 absbits(float f) {
    return __float_as_uint(f) & 0x7fffffffu;
}
__device__ __forceinline__ u64 umax64(u64 a, u64 b) { return a > b ? a : b; }
__device__ __forceinline__ u64 shfl_xor_u64(u64 v, int d) {
    u32 lo = (u32)v, hi = (u32)(v >> 32);
    lo = __shfl_xor_sync(0xffffffffu, lo, d);
    hi = __shfl_xor_sync(0xffffffffu, hi, d);
    return ((u64)hi << 32) | lo;
}
__device__ __forceinline__ u32 smem_addr(const void* p) {
    u32 a;
    asm("{ .reg .u64 t; cvta.to.shared.u64 t, %1; cvt.u32.u64 %0, t; }"
        : "=r"(a) : "l"(p));
    return a;
}
__device__ __forceinline__ void mbar_wait(u32 mb) {
    u32 done;
    asm volatile(
        "{\n\t.reg .pred p;\n\t"
        "mbarrier.try_wait.parity.acquire.cta.shared::cta.b64 p, [%1], 0;\n\t"
        "selp.b32 %0, 1, 0, p;\n\t}"
        : "=r"(done) : "r"(mb) : "memory");
    while (!done) {
        asm volatile(
            "{\n\t.reg .pred p;\n\t"
            "mbarrier.try_wait.parity.acquire.cta.shared::cta.b64 p, [%1], 0, 0x989680;\n\t"
            "selp.b32 %0, 1, 0, p;\n\t}"
            : "=r"(done) : "r"(mb) : "memory");
    }
}

// First index > bound inside tile whose absbits == val, or -1.
__device__ __forceinline__ int find_next(u32 em, int tile, int bound, int lane) {
    int base = tile * 128 + lane * 4;
    int rel = bound - base;                  // element j excluded iff j <= rel
    u32 emm = em;
    if (rel >= 3) emm = 0;
    else if (rel >= 0) emm &= (0xFu << (rel + 1));
    u32 bl = __ballot_sync(0xffffffffu, emm != 0);
    if (!bl) return -1;
    int lf = __ffs((int)bl) - 1;
    u32 pk = __shfl_sync(0xffffffffu, emm, lf);
    return tile * 128 + lf * 4 + (__ffs((int)pk) - 1);
}

__global__ void __launch_bounds__(256, 8)
detect_peaks_kernel(const float* __restrict__ x, float* __restrict__ out, int nrows) {
    __shared__ alignas(16) float buf[HALFN];       // 16 KB: first half-row
    __shared__ u32 tileMax[64];
    __shared__ alignas(8) u64 mbar;

    const int row  = blockIdx.x;
    const int tid  = threadIdx.x;
    const int lane = tid & 31;
    const int warp = tid >> 5;               // 0..7
    const u32 FULL = 0xffffffffu;

    const float* xr = x + (size_t)row * NT;
    const u32 mb = smem_addr(&mbar);
    const u32 db = smem_addr(buf);

    if (tid == 0)
        asm volatile("mbarrier.init.shared.b64 [%0], 1;" :: "r"(mb) : "memory");
    __syncthreads();
    if (tid == 0) {
        asm volatile("mbarrier.arrive.expect_tx.shared.b64 _, [%0], %1;"
                     :: "r"(mb), "r"(HALFN * 4) : "memory");
        asm volatile("cp.async.bulk.shared::cta.global.mbarrier::complete_tx::bytes "
                     "[%0], [%1], %2, [%3];"
                     :: "r"(db), "l"(xr), "r"(HALFN * 4), "r"(mb) : "memory");
    }

    // ---- second half via LDG (front-batched; overlaps TMA arrival) ----
    const float4* g2 = (const float4*)(xr + HALFN);
    float4 v[4];
#pragma unroll
    for (int k = 0; k < 4; k++) v[k] = g2[tid + 256 * k];

#pragma unroll
    for (int k = 0; k < 4; k++) {
        float m01 = fmaxf(fabsf(v[k].x), fabsf(v[k].y));
        float m23 = fmaxf(fabsf(v[k].z), fabsf(v[k].w));
        float m   = fmaxf(m01, m23);
        u32 m1 = __reduce_max_sync(FULL, __float_as_uint(m));
        if (lane == 0) tileMax[32 + warp + 8 * k] = m1;
    }

    // ---- first half from smem after TMA lands ----
    mbar_wait(mb);
    const float4* sb = (const float4*)buf;
#pragma unroll
    for (int k = 0; k < 4; k++) {
        float4 w = sb[tid + 256 * k];
        float m01 = fmaxf(fabsf(w.x), fabsf(w.y));
        float m23 = fmaxf(fabsf(w.z), fabsf(w.w));
        float m   = fmaxf(m01, m23);
        u32 m1 = __reduce_max_sync(FULL, __float_as_uint(m));
        if (lane == 0) tileMax[warp + 8 * k] = m1;
    }
    __syncthreads();

    if (warp != 0) return;

    // ---- selection (warp 0): best-first over tile maxima ----
    u64 keys[2];
#pragma unroll
    for (int q = 0; q < 2; q++) {
        int t = lane + 32 * q;
        keys[q] = ((u64)tileMax[t] << 32) | (u32)(~(u32)(t * 128));
    }
    u64 pend = 0;
    int pendIdx = -1;

    float rv0 = 0.0f, rv1 = 0.0f;
    int   ri0 = 0,    ri1 = 0;
    int found = 0;

    for (int it = 0; it < 192 && found < 2; it++) {
        u64 best = umax64(umax64(keys[0], keys[1]), pend);
#pragma unroll
        for (int s = 16; s > 0; s >>= 1) best = umax64(best, shfl_xor_u64(best, s));
        if (best == 0ull) break;

        bool wasPend = (best == pend && pend != 0ull);
        if (wasPend) pend = 0;
        if (keys[0] == best) keys[0] = 0;
        if (keys[1] == best) keys[1] = 0;

        u32 val = (u32)(best >> 32);
        int tile, idxV;
        if (wasPend) { idxV = pendIdx; tile = idxV >> 7; }
        else         { tile = (int)((~(u32)(best & 0xffffffffull)) >> 7); idxV = -1; }

        // rescan tile: smem for first half, L1-hot gmem for second
        float4 tv = (tile < 32) ? sb[tile * 32 + lane]
                                : ((const float4*)(xr + tile * 128))[lane];
        u32 em = (u32)(absbits(tv.x) == val)        |
                 ((u32)(absbits(tv.y) == val) << 1) |
                 ((u32)(absbits(tv.z) == val) << 2) |
                 ((u32)(absbits(tv.w) == val) << 3);
        if (!wasPend) idxV = find_next(em, tile, tile * 128 - 1, lane);
        int nxt = find_next(em, tile, idxV, lane);
        if (nxt >= 0) { pend = ((u64)val << 32) | (u32)(~(u32)nxt); pendIdx = nxt; }

        // verify idxV against window max using tile bounds (smem)
        int lo = max(idxV - HALF, 0);
        int hi = min(idxV + HALF, NT - 1);
        int ta = lo >> 7, tb = hi >> 7;
        int t = ta + lane;
        u32 tm = (t <= tb) ? tileMax[t] : 0u;
        u32 bound = __reduce_max_sync(FULL, tm);

        bool accept = (bound <= val);
        if (!accept) {
            bool fullt = (t <= tb) && (t * 128 >= lo) && (t * 128 + 127 <= hi);
            if (__reduce_max_sync(FULL, fullt ? tm : 0u) > val) continue;
            // ambiguous edge tiles: exact window max from gmem (rare)
            u32 mbx = 0;
            int base = idxV - HALF;
#pragma unroll
            for (int rr = 0; rr < 10; rr++) {
                int off = lane + 32 * rr;
                int p = min(max(base + off, 0), NT - 1);
                u32 xb = absbits(__ldg(xr + p));
                if (off < WIN) mbx = max(mbx, xb);
            }
            if (__reduce_max_sync(FULL, mbx) > val) continue;
            accept = true;
        }

        if (found == 0) { rv0 = __uint_as_float(val); ri0 = idxV; }
        else            { rv1 = __uint_as_float(val); ri1 = idxV; }
        found++;
    }

    if (lane == 0) {
        if (found < 2) {                 // <2 survivors: next-best score is 0
            rv1 = 0.0f;
            ri1 = (found >= 1 && ri0 == 0) ? 1 : 0;
        }
        out[row * 2 + 0] = rv0;
        out[row * 2 + 1] = rv1;
        out[(size_t)nrows * 2 + row * 2 + 0] = (float)ri0;
        out[(size_t)nrows * 2 + row * 2 + 1] = (float)ri1;
    }
}

extern "C" void kernel_launch(void* const* d_in, const int* in_sizes, int n_in,
                              void* d_out, int out_size) {
    const float* x = (const float*)d_in[0];
    float* out = (float*)d_out;
    int nrows = in_sizes[0] / NT;   // 6144
    detect_peaks_kernel<<<nrows, 256>>>(x, out, nrows);
}

// round 15
// speedup vs baseline: 1.2373x; 1.0386x over previous
#include <cuda_runtime.h>
#include <cstdint>

// DetectPeaksTM: per-row sliding max (K=301) NMS + top-2 (value, index).
// Candidate-based (survivor == max of its aligned 128-tile). One row per
// 256-thread CTA. The row (32 KB) is fetched with a single cp.async.bulk
// (TMA) into smem; tile maxima via REDUX from smem; warp 0 recovers indices
// and verifies candidates entirely from smem.
//
// CONVERGED: sustained 6.2 TB/s == sm_103a path-independent LTS read cap;
// traffic == input size (single pass). Verified best across 14 variants.

#define NT    8192
#define HALF  150
#define WIN   301

typedef unsigned long long u64;
typedef unsigned int u32;

__device__ __forceinline__ u32 absbits(float f) {
    return __float_as_uint(f) & 0x7fffffffu;
}
__device__ __forceinline__ u64 umax64(u64 a, u64 b) { return a > b ? a : b; }
__device__ __forceinline__ u64 shfl_xor_u64(u64 v, int d) {
    u32 lo = (u32)v, hi = (u32)(v >> 32);
    lo = __shfl_xor_sync(0xffffffffu, lo, d);
    hi = __shfl_xor_sync(0xffffffffu, hi, d);
    return ((u64)hi << 32) | lo;
}
__device__ __forceinline__ u32 smem_addr(const void* p) {
    u32 a;
    asm("{ .reg .u64 t; cvta.to.shared.u64 t, %1; cvt.u32.u64 %0, t; }"
        : "=r"(a) : "l"(p));
    return a;
}

// First index > bound inside tile whose absbits == val, or -1.
__device__ __forceinline__ int find_next(u32 em, int tile, int bound, int lane) {
    int base = tile * 128 + lane * 4;
    int rel = bound - base;                  // element j excluded iff j <= rel
    u32 emm = em;
    if (rel >= 3) emm = 0;
    else if (rel >= 0) emm &= (0xFu << (rel + 1));
    u32 bl = __ballot_sync(0xffffffffu, emm != 0);
    if (!bl) return -1;
    int lf = __ffs((int)bl) - 1;
    u32 pk = __shfl_sync(0xffffffffu, emm, lf);
    return tile * 128 + lf * 4 + (__ffs((int)pk) - 1);
}

__global__ void __launch_bounds__(256)
detect_peaks_kernel(const float* __restrict__ x, float* __restrict__ out, int nrows) {
    __shared__ alignas(16) float buf[NT];          // 32 KB row
    __shared__ u32 tileMax[64];
    __shared__ alignas(8) u64 mbar;

    const int row  = blockIdx.x;
    const int tid  = threadIdx.x;
    const int lane = tid & 31;
    const int warp = tid >> 5;               // 0..7
    const u32 FULL = 0xffffffffu;

    const u32 mb = smem_addr(&mbar);
    const u32 db = smem_addr(buf);

    if (tid == 0) {
        asm volatile("mbarrier.init.shared.b64 [%0], 1;" :: "r"(mb) : "memory");
    }
    __syncthreads();
    if (tid == 0) {
        asm volatile("mbarrier.arrive.expect_tx.shared.b64 _, [%0], %1;"
                     :: "r"(mb), "r"(NT * 4) : "memory");
        asm volatile("cp.async.bulk.shared::cta.global.mbarrier::complete_tx::bytes "
                     "[%0], [%1], %2, [%3];"
                     :: "r"(db), "l"(x + (size_t)row * NT), "r"(NT * 4), "r"(mb)
                     : "memory");
    }
    // wait (parity 0)
    {
        u32 done;
        asm volatile(
            "{\n\t.reg .pred p;\n\t"
            "mbarrier.try_wait.parity.acquire.cta.shared::cta.b64 p, [%1], 0;\n\t"
            "selp.b32 %0, 1, 0, p;\n\t}"
            : "=r"(done) : "r"(mb) : "memory");
        while (!done) {
            asm volatile(
                "{\n\t.reg .pred p;\n\t"
                "mbarrier.try_wait.parity.acquire.cta.shared::cta.b64 p, [%1], 0, 0x989680;\n\t"
                "selp.b32 %0, 1, 0, p;\n\t}"
                : "=r"(done) : "r"(mb) : "memory");
        }
    }

    // ---- tile maxima from smem ----
    const float4* sb = (const float4*)buf;
#pragma unroll
    for (int k = 0; k < 8; k++) {
        float4 v = sb[tid + 256 * k];
        float m01 = fmaxf(fabsf(v.x), fabsf(v.y));
        float m23 = fmaxf(fabsf(v.z), fabsf(v.w));
        float m   = fmaxf(m01, m23);
        u32 m1 = __reduce_max_sync(FULL, __float_as_uint(m));
        if (lane == 0) tileMax[warp + 8 * k] = m1;   // tile = warp + 8k
    }
    __syncthreads();

    if (warp != 0) return;

    // ---- selection (warp 0): best-first over tile maxima, all from smem ----
    u64 keys[2];
#pragma unroll
    for (int q = 0; q < 2; q++) {
        int t = lane + 32 * q;
        keys[q] = ((u64)tileMax[t] << 32) | (u32)(~(u32)(t * 128));
    }
    u64 pend = 0;        // at most one pending same-value occurrence (uniform)
    int pendIdx = -1;

    float rv0 = 0.0f, rv1 = 0.0f;
    int   ri0 = 0,    ri1 = 0;
    int found = 0;

    for (int it = 0; it < 192 && found < 2; it++) {
        u64 best = umax64(umax64(keys[0], keys[1]), pend);
#pragma unroll
        for (int s = 16; s > 0; s >>= 1) best = umax64(best, shfl_xor_u64(best, s));
        if (best == 0ull) break;

        bool wasPend = (best == pend && pend != 0ull);
        if (wasPend) pend = 0;
        if (keys[0] == best) keys[0] = 0;
        if (keys[1] == best) keys[1] = 0;

        u32 val = (u32)(best >> 32);
        int tile, idxV;
        if (wasPend) { idxV = pendIdx; tile = idxV >> 7; }
        else         { tile = (int)((~(u32)(best & 0xffffffffull)) >> 7); idxV = -1; }

        // rescan tile (smem) for occurrence chain
        float4 tv = sb[tile * 32 + lane];
        u32 em = (u32)(absbits(tv.x) == val)        |
                 ((u32)(absbits(tv.y) == val) << 1) |
                 ((u32)(absbits(tv.z) == val) << 2) |
                 ((u32)(absbits(tv.w) == val) << 3);
        if (!wasPend) idxV = find_next(em, tile, tile * 128 - 1, lane);
        int nxt = find_next(em, tile, idxV, lane);
        if (nxt >= 0) { pend = ((u64)val << 32) | (u32)(~(u32)nxt); pendIdx = nxt; }

        // verify idxV against window max using tile bounds (smem)
        int lo = max(idxV - HALF, 0);
        int hi = min(idxV + HALF, NT - 1);
        int ta = lo >> 7, tb = hi >> 7;
        int t = ta + lane;
        u32 tm = (t <= tb) ? tileMax[t] : 0u;
        u32 bound = __reduce_max_sync(FULL, tm);

        bool accept = (bound <= val);
        if (!accept) {
            bool fullt = (t <= tb) && (t * 128 >= lo) && (t * 128 + 127 <= hi);
            if (__reduce_max_sync(FULL, fullt ? tm : 0u) > val) continue;
            // ambiguous edge tiles: exact window max from smem
            u32 mbx = 0;
            int base = idxV - HALF;
#pragma unroll
            for (int rr = 0; rr < 10; rr++) {
                int off = lane + 32 * rr;
                int p = min(max(base + off, 0), NT - 1);
                u32 xb = absbits(buf[p]);
                if (off < WIN) mbx = max(mbx, xb);
            }
            if (__reduce_max_sync(FULL, mbx) > val) continue;
            accept = true;
        }

        if (found == 0) { rv0 = __uint_as_float(val); ri0 = idxV; }
        else            { rv1 = __uint_as_float(val); ri1 = idxV; }
        found++;
    }

    if (lane == 0) {
        if (found < 2) {                 // <2 survivors: next-best score is 0
            rv1 = 0.0f;
            ri1 = (found >= 1 && ri0 == 0) ? 1 : 0;
        }
        out[row * 2 + 0] = rv0;
        out[row * 2 + 1] = rv1;
        out[(size_t)nrows * 2 + row * 2 + 0] = (float)ri0;
        out[(size_t)nrows * 2 + row * 2 + 1] = (float)ri1;
    }
}

extern "C" void kernel_launch(void* const* d_in, const int* in_sizes, int n_in,
                              void* d_out, int out_size) {
    const float* x = (const float*)d_in[0];
    float* out = (float*)d_out;
    int nrows = in_sizes[0] / NT;   // 6144
    detect_peaks_kernel<<<nrows, 256>>>(x, out, nrows);
}

// round 16
// speedup vs baseline: 1.2635x; 1.0212x over previous
#include <cuda_runtime.h>
#include <cstdint>

// DetectPeaksTM: per-row sliding max (K=301) NMS + top-2 (value, index).
// Candidate-based (survivor == max of its aligned 128-tile). One row per
// 256-thread CTA. The row (32 KB) is fetched as 4 chunked cp.async.bulk
// (TMA) ops with independent mbarriers; tile-max reduction of chunk c
// overlaps arrival of chunks c+1.. Selection (warp 0) recovers indices and
// verifies candidates entirely from smem.

#define NT     8192
#define HALF   150
#define WIN    301
#define NCHUNK 4
#define CELEM  (NT / NCHUNK)      // 2048 floats = 8 KB per chunk

typedef unsigned long long u64;
typedef unsigned int u32;

__device__ __forceinline__ u32 absbits(float f) {
    return __float_as_uint(f) & 0x7fffffffu;
}
__device__ __forceinline__ u64 umax64(u64 a, u64 b) { return a > b ? a : b; }
__device__ __forceinline__ u64 shfl_xor_u64(u64 v, int d) {
    u32 lo = (u32)v, hi = (u32)(v >> 32);
    lo = __shfl_xor_sync(0xffffffffu, lo, d);
    hi = __shfl_xor_sync(0xffffffffu, hi, d);
    return ((u64)hi << 32) | lo;
}
__device__ __forceinline__ u32 smem_addr(const void* p) {
    u32 a;
    asm("{ .reg .u64 t; cvta.to.shared.u64 t, %1; cvt.u32.u64 %0, t; }"
        : "=r"(a) : "l"(p));
    return a;
}
__device__ __forceinline__ void mbar_wait(u32 mb) {
    u32 done;
    asm volatile(
        "{\n\t.reg .pred p;\n\t"
        "mbarrier.try_wait.parity.acquire.cta.shared::cta.b64 p, [%1], 0;\n\t"
        "selp.b32 %0, 1, 0, p;\n\t}"
        : "=r"(done) : "r"(mb) : "memory");
    while (!done) {
        asm volatile(
            "{\n\t.reg .pred p;\n\t"
            "mbarrier.try_wait.parity.acquire.cta.shared::cta.b64 p, [%1], 0, 0x989680;\n\t"
            "selp.b32 %0, 1, 0, p;\n\t}"
            : "=r"(done) : "r"(mb) : "memory");
    }
}

// First index > bound inside tile whose absbits == val, or -1.
__device__ __forceinline__ int find_next(u32 em, int tile, int bound, int lane) {
    int base = tile * 128 + lane * 4;
    int rel = bound - base;                  // element j excluded iff j <= rel
    u32 emm = em;
    if (rel >= 3) emm = 0;
    else if (rel >= 0) emm &= (0xFu << (rel + 1));
    u32 bl = __ballot_sync(0xffffffffu, emm != 0);
    if (!bl) return -1;
    int lf = __ffs((int)bl) - 1;
    u32 pk = __shfl_sync(0xffffffffu, emm, lf);
    return tile * 128 + lf * 4 + (__ffs((int)pk) - 1);
}

__global__ void __launch_bounds__(256)
detect_peaks_kernel(const float* __restrict__ x, float* __restrict__ out, int nrows) {
    __shared__ alignas(16) float buf[NT];          // 32 KB row
    __shared__ u32 tileMax[64];
    __shared__ alignas(8) u64 mbar[NCHUNK];

    const int row  = blockIdx.x;
    const int tid  = threadIdx.x;
    const int lane = tid & 31;
    const int warp = tid >> 5;               // 0..7
    const u32 FULL = 0xffffffffu;

    const float* xr = x + (size_t)row * NT;

    if (tid < NCHUNK) {
        u32 m = smem_addr(&mbar[tid]);
        asm volatile("mbarrier.init.shared.b64 [%0], 1;" :: "r"(m) : "memory");
    }
    __syncthreads();
    if (tid == 0) {
#pragma unroll
        for (int c = 0; c < NCHUNK; c++) {
            u32 m = smem_addr(&mbar[c]);
            u32 d = smem_addr(buf + c * CELEM);
            asm volatile("mbarrier.arrive.expect_tx.shared.b64 _, [%0], %1;"
                         :: "r"(m), "r"(CELEM * 4) : "memory");
            asm volatile("cp.async.bulk.shared::cta.global.mbarrier::complete_tx::bytes "
                         "[%0], [%1], %2, [%3];"
                         :: "r"(d), "l"(xr + c * CELEM), "r"(CELEM * 4), "r"(m)
                         : "memory");
        }
    }

    // ---- tile maxima, chunk-pipelined: reduce chunk c as it lands ----
    const float4* sb = (const float4*)buf;
#pragma unroll
    for (int c = 0; c < NCHUNK; c++) {
        mbar_wait(smem_addr(&mbar[c]));
#pragma unroll
        for (int k = 0; k < 2; k++) {        // 2 float4 per thread per chunk
            float4 v = sb[c * (CELEM / 4) + tid + 256 * k];
            float m01 = fmaxf(fabsf(v.x), fabsf(v.y));
            float m23 = fmaxf(fabsf(v.z), fabsf(v.w));
            float m   = fmaxf(m01, m23);
            u32 m1 = __reduce_max_sync(FULL, __float_as_uint(m));
            if (lane == 0) tileMax[c * 16 + warp + 8 * k] = m1;
        }
    }
    __syncthreads();

    if (warp != 0) return;

    // ---- selection (warp 0): best-first over tile maxima, all from smem ----
    u64 keys[2];
#pragma unroll
    for (int q = 0; q < 2; q++) {
        int t = lane + 32 * q;
        keys[q] = ((u64)tileMax[t] << 32) | (u32)(~(u32)(t * 128));
    }
    u64 pend = 0;        // at most one pending same-value occurrence (uniform)
    int pendIdx = -1;

    float rv0 = 0.0f, rv1 = 0.0f;
    int   ri0 = 0,    ri1 = 0;
    int found = 0;

    for (int it = 0; it < 192 && found < 2; it++) {
        u64 best = umax64(umax64(keys[0], keys[1]), pend);
#pragma unroll
        for (int s = 16; s > 0; s >>= 1) best = umax64(best, shfl_xor_u64(best, s));
        if (best == 0ull) break;

        bool wasPend = (best == pend && pend != 0ull);
        if (wasPend) pend = 0;
        if (keys[0] == best) keys[0] = 0;
        if (keys[1] == best) keys[1] = 0;

        u32 val = (u32)(best >> 32);
        int tile, idxV;
        if (wasPend) { idxV = pendIdx; tile = idxV >> 7; }
        else         { tile = (int)((~(u32)(best & 0xffffffffull)) >> 7); idxV = -1; }

        // rescan tile (smem) for occurrence chain
        float4 tv = sb[tile * 32 + lane];
        u32 em = (u32)(absbits(tv.x) == val)        |
                 ((u32)(absbits(tv.y) == val) << 1) |
                 ((u32)(absbits(tv.z) == val) << 2) |
                 ((u32)(absbits(tv.w) == val) << 3);
        if (!wasPend) idxV = find_next(em, tile, tile * 128 - 1, lane);
        int nxt = find_next(em, tile, idxV, lane);
        if (nxt >= 0) { pend = ((u64)val << 32) | (u32)(~(u32)nxt); pendIdx = nxt; }

        // verify idxV against window max using tile bounds (smem)
        int lo = max(idxV - HALF, 0);
        int hi = min(idxV + HALF, NT - 1);
        int ta = lo >> 7, tb = hi >> 7;
        int t = ta + lane;
        u32 tm = (t <= tb) ? tileMax[t] : 0u;
        u32 bound = __reduce_max_sync(FULL, tm);

        bool accept = (bound <= val);
        if (!accept) {
            bool fullt = (t <= tb) && (t * 128 >= lo) && (t * 128 + 127 <= hi);
            if (__reduce_max_sync(FULL, fullt ? tm : 0u) > val) continue;
            // ambiguous edge tiles: exact window max from smem
            u32 mbx = 0;
            int base = idxV - HALF;
#pragma unroll
            for (int rr = 0; rr < 10; rr++) {
                int off = lane + 32 * rr;
                int p = min(max(base + off, 0), NT - 1);
                u32 xb = absbits(buf[p]);
                if (off < WIN) mbx = max(mbx, xb);
            }
            if (__reduce_max_sync(FULL, mbx) > val) continue;
            accept = true;
        }

        if (found == 0) { rv0 = __uint_as_float(val); ri0 = idxV; }
        else            { rv1 = __uint_as_float(val); ri1 = idxV; }
        found++;
    }

    if (lane == 0) {
        if (found < 2) {                 // <2 survivors: next-best score is 0
            rv1 = 0.0f;
            ri1 = (found >= 1 && ri0 == 0) ? 1 : 0;
        }
        out[row * 2 + 0] = rv0;
        out[row * 2 + 1] = rv1;
        out[(size_t)nrows * 2 + row * 2 + 0] = (float)ri0;
        out[(size_t)nrows * 2 + row * 2 + 1] = (float)ri1;
    }
}

extern "C" void kernel_launch(void* const* d_in, const int* in_sizes, int n_in,
                              void* d_out, int out_size) {
    const float* x = (const float*)d_in[0];
    float* out = (float*)d_out;
    int nrows = in_sizes[0] / NT;   // 6144
    detect_peaks_kernel<<<nrows, 256>>>(x, out, nrows);
}

// round 17
// speedup vs baseline: 1.2647x; 1.0010x over previous
#include <cuda_runtime.h>
#include <cstdint>

// DetectPeaksTM: per-row sliding max (K=301) NMS + top-2 (value, index).
// Input : xcorr [32,3,64,8192] fp32 -> 6144 rows; Output: top-2 scores+idx.
//
// FINAL (converged): single pass at the sm_103a path-independent LTS read
// cap (~6.2 TB/s sustained; traffic == input size). Algorithm:
//   - a NMS survivor must equal the max of its aligned 128-tile (tile width
//     128 <= 151, so the tile lies fully inside the +-150 window)
//   - one 256-thread CTA per row; row fetched by one cp.async.bulk (TMA)
//     into smem; 64 tile maxima via FMNMX + REDUX.SYNC (values only)
//   - warp 0 selects candidates best-first (val desc, idx asc = lax.top_k
//     tie order), recovers indices lazily by rescanning the smem tile,
//     verifies each candidate against the 301-window via tile-max bounds
//     (exact window scan only for rare ambiguous edge cases).

#define NT    8192
#define HALF  150
#define WIN   301

typedef unsigned long long u64;
typedef unsigned int u32;

__device__ __forceinline__ u32 absbits(float f) {
    return __float_as_uint(f) & 0x7fffffffu;
}
__device__ __forceinline__ u64 umax64(u64 a, u64 b) { return a > b ? a : b; }
__device__ __forceinline__ u64 shfl_xor_u64(u64 v, int d) {
    u32 lo = (u32)v, hi = (u32)(v >> 32);
    lo = __shfl_xor_sync(0xffffffffu, lo, d);
    hi = __shfl_xor_sync(0xffffffffu, hi, d);
    return ((u64)hi << 32) | lo;
}
__device__ __forceinline__ u32 smem_addr(const void* p) {
    u32 a;
    asm("{ .reg .u64 t; cvta.to.shared.u64 t, %1; cvt.u32.u64 %0, t; }"
        : "=r"(a) : "l"(p));
    return a;
}

// First index > bound inside tile whose absbits == val, or -1.
__device__ __forceinline__ int find_next(u32 em, int tile, int bound, int lane) {
    int base = tile * 128 + lane * 4;
    int rel = bound - base;                  // element j excluded iff j <= rel
    u32 emm = em;
    if (rel >= 3) emm = 0;
    else if (rel >= 0) emm &= (0xFu << (rel + 1));
    u32 bl = __ballot_sync(0xffffffffu, emm != 0);
    if (!bl) return -1;
    int lf = __ffs((int)bl) - 1;
    u32 pk = __shfl_sync(0xffffffffu, emm, lf);
    return tile * 128 + lf * 4 + (__ffs((int)pk) - 1);
}

__global__ void __launch_bounds__(256)
detect_peaks_kernel(const float* __restrict__ x, float* __restrict__ out, int nrows) {
    __shared__ alignas(16) float buf[NT];          // 32 KB row
    __shared__ u32 tileMax[64];
    __shared__ alignas(8) u64 mbar;

    const int row  = blockIdx.x;
    const int tid  = threadIdx.x;
    const int lane = tid & 31;
    const int warp = tid >> 5;               // 0..7
    const u32 FULL = 0xffffffffu;

    const u32 mb = smem_addr(&mbar);
    const u32 db = smem_addr(buf);

    if (tid == 0) {
        asm volatile("mbarrier.init.shared.b64 [%0], 1;" :: "r"(mb) : "memory");
    }
    __syncthreads();
    if (tid == 0) {
        asm volatile("mbarrier.arrive.expect_tx.shared.b64 _, [%0], %1;"
                     :: "r"(mb), "r"(NT * 4) : "memory");
        asm volatile("cp.async.bulk.shared::cta.global.mbarrier::complete_tx::bytes "
                     "[%0], [%1], %2, [%3];"
                     :: "r"(db), "l"(x + (size_t)row * NT), "r"(NT * 4), "r"(mb)
                     : "memory");
    }
    // wait (parity 0)
    {
        u32 done;
        asm volatile(
            "{\n\t.reg .pred p;\n\t"
            "mbarrier.try_wait.parity.acquire.cta.shared::cta.b64 p, [%1], 0;\n\t"
            "selp.b32 %0, 1, 0, p;\n\t}"
            : "=r"(done) : "r"(mb) : "memory");
        while (!done) {
            asm volatile(
                "{\n\t.reg .pred p;\n\t"
                "mbarrier.try_wait.parity.acquire.cta.shared::cta.b64 p, [%1], 0, 0x989680;\n\t"
                "selp.b32 %0, 1, 0, p;\n\t}"
                : "=r"(done) : "r"(mb) : "memory");
        }
    }

    // ---- tile maxima from smem ----
    const float4* sb = (const float4*)buf;
#pragma unroll
    for (int k = 0; k < 8; k++) {
        float4 v = sb[tid + 256 * k];
        float m01 = fmaxf(fabsf(v.x), fabsf(v.y));
        float m23 = fmaxf(fabsf(v.z), fabsf(v.w));
        float m   = fmaxf(m01, m23);
        u32 m1 = __reduce_max_sync(FULL, __float_as_uint(m));
        if (lane == 0) tileMax[warp + 8 * k] = m1;   // tile = warp + 8k
    }
    __syncthreads();

    if (warp != 0) return;

    // ---- selection (warp 0): best-first over tile maxima, all from smem ----
    u64 keys[2];
#pragma unroll
    for (int q = 0; q < 2; q++) {
        int t = lane + 32 * q;
        keys[q] = ((u64)tileMax[t] << 32) | (u32)(~(u32)(t * 128));
    }
    u64 pend = 0;        // at most one pending same-value occurrence (uniform)
    int pendIdx = -1;

    float rv0 = 0.0f, rv1 = 0.0f;
    int   ri0 = 0,    ri1 = 0;
    int found = 0;

    for (int it = 0; it < 192 && found < 2; it++) {
        u64 best = umax64(umax64(keys[0], keys[1]), pend);
#pragma unroll
        for (int s = 16; s > 0; s >>= 1) best = umax64(best, shfl_xor_u64(best, s));
        if (best == 0ull) break;

        bool wasPend = (best == pend && pend != 0ull);
        if (wasPend) pend = 0;
        if (keys[0] == best) keys[0] = 0;
        if (keys[1] == best) keys[1] = 0;

        u32 val = (u32)(best >> 32);
        int tile, idxV;
        if (wasPend) { idxV = pendIdx; tile = idxV >> 7; }
        else         { tile = (int)((~(u32)(best & 0xffffffffull)) >> 7); idxV = -1; }

        // rescan tile (smem) for occurrence chain
        float4 tv = sb[tile * 32 + lane];
        u32 em = (u32)(absbits(tv.x) == val)        |
                 ((u32)(absbits(tv.y) == val) << 1) |
                 ((u32)(absbits(tv.z) == val) << 2) |
                 ((u32)(absbits(tv.w) == val) << 3);
        if (!wasPend) idxV = find_next(em, tile, tile * 128 - 1, lane);
        int nxt = find_next(em, tile, idxV, lane);
        if (nxt >= 0) { pend = ((u64)val << 32) | (u32)(~(u32)nxt); pendIdx = nxt; }

        // verify idxV against window max using tile bounds (smem)
        int lo = max(idxV - HALF, 0);
        int hi = min(idxV + HALF, NT - 1);
        int ta = lo >> 7, tb = hi >> 7;
        int t = ta + lane;
        u32 tm = (t <= tb) ? tileMax[t] : 0u;
        u32 bound = __reduce_max_sync(FULL, tm);

        bool accept = (bound <= val);
        if (!accept) {
            bool fullt = (t <= tb) && (t * 128 >= lo) && (t * 128 + 127 <= hi);
            if (__reduce_max_sync(FULL, fullt ? tm : 0u) > val) continue;
            // ambiguous edge tiles: exact window max from smem
            u32 mbx = 0;
            int base = idxV - HALF;
#pragma unroll
            for (int rr = 0; rr < 10; rr++) {
                int off = lane + 32 * rr;
                int p = min(max(base + off, 0), NT - 1);
                u32 xb = absbits(buf[p]);
                if (off < WIN) mbx = max(mbx, xb);
            }
            if (__reduce_max_sync(FULL, mbx) > val) continue;
            accept = true;
        }

        if (found == 0) { rv0 = __uint_as_float(val); ri0 = idxV; }
        else            { rv1 = __uint_as_float(val); ri1 = idxV; }
        found++;
    }

    if (lane == 0) {
        if (found < 2) {                 // <2 survivors: next-best score is 0
            rv1 = 0.0f;
            ri1 = (found >= 1 && ri0 == 0) ? 1 : 0;
        }
        out[row * 2 + 0] = rv0;
        out[row * 2 + 1] = rv1;
        out[(size_t)nrows * 2 + row * 2 + 0] = (float)ri0;
        out[(size_t)nrows * 2 + row * 2 + 1] = (float)ri1;
    }
}

extern "C" void kernel_launch(void* const* d_in, const int* in_sizes, int n_in,
                              void* d_out, int out_size) {
    const float* x = (const float*)d_in[0];
    float* out = (float*)d_out;
    int nrows = in_sizes[0] / NT;   // 6144
    detect_peaks_kernel<<<nrows, 256>>>(x, out, nrows);
}